// round 1
// baseline (speedup 1.0000x reference)
#include <cuda_runtime.h>
#include <cuda_bf16.h>

// Problem constants (from reference setup_inputs):
//   B=64 batches, K=16 candidates, L_cand=32, L_src=64, pad_id=0
#define B_SZ   64
#define K_SZ   16
#define LC_SZ  32
#define LS_SZ  64

__global__ void __launch_bounds__(256, 8)
ngram_rerank_kernel(const int* __restrict__ cand,   // [B, K, LC]
                    const int* __restrict__ src,    // [B, LS]
                    float* __restrict__ out_f,      // full layout, or null
                    int*   __restrict__ out_i)      // tokens-only layout, or null
{
    const int b   = blockIdx.x;
    const int tid = threadIdx.x;

    __shared__ int s[LS_SZ];
    __shared__ int c[K_SZ * LC_SZ];
    __shared__ int r2_sh;
    __shared__ int dot_sh[K_SZ];
    __shared__ int c2_sh[K_SZ];
    __shared__ float scores[K_SZ];
    __shared__ int order[K_SZ];

    if (tid < LS_SZ) s[tid] = src[b * LS_SZ + tid];
    if (tid < K_SZ) { dot_sh[tid] = 0; c2_sh[tid] = 0; }
    if (tid == 0)   r2_sh = 0;
    for (int i = tid; i < K_SZ * LC_SZ; i += blockDim.x)
        c[i] = cand[b * (K_SZ * LC_SZ) + i];
    __syncthreads();

    // ||r||^2 = sum over nonpad src tokens of their count in src
    if (tid < LS_SZ) {
        const int t = s[tid];
        if (t != 0) {
            int acc = 0;
            #pragma unroll
            for (int j = 0; j < LS_SZ; j++) acc += (s[j] == t);
            atomicAdd(&r2_sh, acc);
        }
    }

    // dot[k] and ||c_k||^2 : one work item per (k, j) candidate position
    for (int w = tid; w < K_SZ * LC_SZ; w += blockDim.x) {
        const int k = w >> 5;      // LC_SZ == 32
        const int t = c[w];
        if (t != 0) {
            int d = 0;
            #pragma unroll
            for (int i = 0; i < LS_SZ; i++) d += (s[i] == t);
            int cc = 0;
            const int* ck = &c[k * LC_SZ];
            #pragma unroll
            for (int i = 0; i < LC_SZ; i++) cc += (ck[i] == t);
            if (d) atomicAdd(&dot_sh[k], d);
            atomicAdd(&c2_sh[k], cc);
        }
    }
    __syncthreads();

    // scores[k] = 1 - dot / (||r|| * ||c||), IEEE ops to match XLA fp32 exactly
    if (tid < K_SZ) {
        const float rn = __fsqrt_rn((float)r2_sh);
        const float cn = __fsqrt_rn((float)c2_sh[tid]);
        const float denom = __fmul_rn(rn, cn);
        scores[tid] = __fsub_rn(1.0f, __fdiv_rn((float)dot_sh[tid], denom));
    }
    __syncthreads();

    // Stable descending sort of 16 scores (matches jnp.argsort(-scores), stable).
    if (tid == 0) {
        #pragma unroll
        for (int i = 0; i < K_SZ; i++) order[i] = i;
        for (int i = 1; i < K_SZ; i++) {
            const int oi = order[i];
            const float si = scores[oi];
            int j = i - 1;
            while (j >= 0 && scores[order[j]] < si) {
                order[j + 1] = order[j];
                j--;
            }
            order[j + 1] = oi;
        }
    }
    __syncthreads();

    const int best = order[0];

    if (out_f != nullptr) {
        // layout: [tokens B*LC | lengths B | scores_sorted B*K], all fp32
        if (tid < LC_SZ)
            out_f[b * LC_SZ + tid] = (float)c[best * LC_SZ + tid];
        if (tid == 0) {
            int len = 0;
            #pragma unroll
            for (int i = 0; i < LC_SZ; i++) len += (c[best * LC_SZ + i] != 0);
            out_f[B_SZ * LC_SZ + b] = (float)len;
        }
        if (tid < K_SZ)
            out_f[B_SZ * LC_SZ + B_SZ + b * K_SZ + tid] = scores[order[tid]];
    } else {
        // tokens only, int32
        if (tid < LC_SZ)
            out_i[b * LC_SZ + tid] = c[best * LC_SZ + tid];
    }
}

extern "C" void kernel_launch(void* const* d_in, const int* in_sizes, int n_in,
                              void* d_out, int out_size)
{
    // Identify tensors by element count (robust to scalar inputs in the list):
    //   candidates: 64*16*32 = 32768,  src_ids: 64*64 = 4096
    const int* cand = nullptr;
    const int* src  = nullptr;
    for (int i = 0; i < n_in; i++) {
        if (in_sizes[i] == B_SZ * K_SZ * LC_SZ) cand = (const int*)d_in[i];
        else if (in_sizes[i] == B_SZ * LS_SZ)   src  = (const int*)d_in[i];
    }

    if (out_size == B_SZ * LC_SZ) {
        // tokens-only int32 output
        ngram_rerank_kernel<<<B_SZ, 256>>>(cand, src, nullptr, (int*)d_out);
    } else {
        // full tuple concatenated as float32: tokens | lengths | scores_sorted
        ngram_rerank_kernel<<<B_SZ, 256>>>(cand, src, (float*)d_out, nullptr);
    }
}

// round 2
// speedup vs baseline: 1.2889x; 1.2889x over previous
#include <cuda_runtime.h>
#include <cuda_bf16.h>

// Problem constants (from reference setup_inputs):
//   B=64 batches, K=16 candidates, L_cand=32, L_src=64, pad_id=0
#define B_SZ   64
#define K_SZ   16
#define LC_SZ  32
#define LS_SZ  64

#define FULL_MASK 0xFFFFFFFFu

// One CTA per batch, one warp per candidate k (16 warps = 512 threads).
// All counting in registers via shuffle broadcast + match + REDUX; no smem
// atomics; parallel stable rank-sort instead of serial insertion sort.
__global__ void __launch_bounds__(512, 2)
ngram_rerank_kernel(const int* __restrict__ cand,   // [B, K, LC]
                    const int* __restrict__ src,    // [B, LS]
                    float* __restrict__ out_f,      // full fp32 layout, or null
                    int*   __restrict__ out_i)      // tokens-only int32, or null
{
    const int b    = blockIdx.x;
    const int tid  = threadIdx.x;
    const int warp = tid >> 5;     // candidate index k
    const int lane = tid & 31;

    // ---- loads: all coalesced, no smem staging ----
    const int* sb = src + b * LS_SZ;
    const int s0 = sb[lane];          // src[0..31]
    const int s1 = sb[lane + 32];     // src[32..63]
    const int t  = cand[b * (K_SZ * LC_SZ) + warp * LC_SZ + lane];

    // ---- fused broadcast loop over the 64 src tokens ----
    // d    : count of t  in src       (for dot[k], valid when t != 0)
    // cnt0 : count of s0 in src       (for r2, valid when s0 != 0)
    // cnt1 : count of s1 in src
    int d = 0, cnt0 = 0, cnt1 = 0;
    #pragma unroll
    for (int i = 0; i < 32; i++) {
        const int sv = __shfl_sync(FULL_MASK, s0, i);
        d    += (sv == t);
        cnt0 += (sv == s0);
        cnt1 += (sv == s1);
    }
    #pragma unroll
    for (int i = 0; i < 32; i++) {
        const int sv = __shfl_sync(FULL_MASK, s1, i);
        d    += (sv == t);
        cnt0 += (sv == s0);
        cnt1 += (sv == s1);
    }

    const int d_val  = (t  != 0) ? d    : 0;
    const int r2_val = ((s0 != 0) ? cnt0 : 0) + ((s1 != 0) ? cnt1 : 0);

    // ||c_k||^2: lanes with equal t form a match group; each nonpad lane
    // contributes the group size.
    const unsigned mm = __match_any_sync(FULL_MASK, t);
    const int c2_val  = (t != 0) ? __popc(mm) : 0;

    // HW warp reductions (REDUX)
    const int dot = __reduce_add_sync(FULL_MASK, d_val);
    const int r2  = __reduce_add_sync(FULL_MASK, r2_val);
    const int c2  = __reduce_add_sync(FULL_MASK, c2_val);

    __shared__ float sc[K_SZ];
    __shared__ int   rank_of[K_SZ];

    if (lane == 0) {
        const float rn = __fsqrt_rn((float)r2);
        const float cn = __fsqrt_rn((float)c2);
        sc[warp] = __fsub_rn(1.0f, __fdiv_rn((float)dot, __fmul_rn(rn, cn)));
    }
    __syncthreads();

    // ---- parallel stable descending rank sort (matches jnp.argsort(-s)) ----
    if (warp == 0 && lane < K_SZ) {
        const float si = sc[lane];
        int rank = 0;
        #pragma unroll
        for (int j = 0; j < K_SZ; j++) {
            const float sj = sc[j];
            rank += (sj > si) || (sj == si && j < lane);
        }
        rank_of[lane] = rank;
        if (out_f != nullptr)
            out_f[B_SZ * LC_SZ + B_SZ + b * K_SZ + rank] = si;  // scores_sorted
    }
    __syncthreads();

    // ---- outputs from the winning warp (rank 0) ----
    if (rank_of[warp] == 0) {
        if (out_f != nullptr) {
            out_f[b * LC_SZ + lane] = (float)t;                 // tokens
            const unsigned nb = __ballot_sync(FULL_MASK, t != 0);
            if (lane == 0)
                out_f[B_SZ * LC_SZ + b] = (float)__popc(nb);    // length
        } else {
            out_i[b * LC_SZ + lane] = t;
        }
    }
}

extern "C" void kernel_launch(void* const* d_in, const int* in_sizes, int n_in,
                              void* d_out, int out_size)
{
    // Identify tensors by element count (robust to scalar inputs in the list):
    //   candidates: 64*16*32 = 32768,  src_ids: 64*64 = 4096
    const int* cand = nullptr;
    const int* src  = nullptr;
    for (int i = 0; i < n_in; i++) {
        if (in_sizes[i] == B_SZ * K_SZ * LC_SZ) cand = (const int*)d_in[i];
        else if (in_sizes[i] == B_SZ * LS_SZ)   src  = (const int*)d_in[i];
    }

    if (out_size == B_SZ * LC_SZ) {
        ngram_rerank_kernel<<<B_SZ, 512>>>(cand, src, nullptr, (int*)d_out);
    } else {
        ngram_rerank_kernel<<<B_SZ, 512>>>(cand, src, (float*)d_out, nullptr);
    }
}

// round 3
// speedup vs baseline: 1.8796x; 1.4583x over previous
#include <cuda_runtime.h>
#include <cuda_bf16.h>
#include <limits.h>

// Problem constants (from reference setup_inputs):
//   B=64 batches, K=16 candidates, L_cand=32, L_src=64, pad_id=0
#define B_SZ   64
#define K_SZ   16
#define LC_SZ  32
#define LS_SZ  64

#define FULL_MASK 0xFFFFFFFFu

// One CTA per batch, one warp per candidate k (16 warps = 512 threads).
// d[k]   : broadcast candidate tokens (32 SHFL), compare vs lane's two src tokens.
// c2[k]  : __match_any + popc.
// r2     : distributed — warp w counts matches against broadcast src positions
//          {2w, 2w+1} in both halves; partials combined in smem by warp 0.
// Sort   : warp 0 does a 16-lane stable descending rank sort in registers.
__global__ void __launch_bounds__(512, 2)
ngram_rerank_kernel(const int* __restrict__ cand,   // [B, K, LC]
                    const int* __restrict__ src,    // [B, LS]
                    float* __restrict__ out_f,      // full fp32 layout, or null
                    int*   __restrict__ out_i)      // tokens-only int32, or null
{
    const int b    = blockIdx.x;
    const int tid  = threadIdx.x;
    const int warp = tid >> 5;     // candidate index k
    const int lane = tid & 31;

    __shared__ int   sm_dot[K_SZ];
    __shared__ int   sm_c2[K_SZ];
    __shared__ int   sm_r2p[K_SZ];
    __shared__ int   sm_rank[K_SZ];

    // ---- coalesced loads ----
    const int* sb = src + b * LS_SZ;
    const int s0 = sb[lane];
    const int s1 = sb[lane + 32];
    const int t  = cand[b * (K_SZ * LC_SZ) + warp * LC_SZ + lane];

    // ---- dot[k]: broadcast candidate tokens, compare vs s0/s1 ----
    // pad candidates masked to -1 (never equals any src token >= 0)
    const int t_m = (t != 0) ? t : -1;
    int d = 0;
    #pragma unroll
    for (int i = 0; i < 32; i++) {
        const int cv = __shfl_sync(FULL_MASK, t_m, i);
        d += (cv == s0);
        d += (cv == s1);
    }

    // ---- ||c_k||^2 via match groups ----
    const unsigned mm = __match_any_sync(FULL_MASK, t);
    const int c2_val  = (t != 0) ? __popc(mm) : 0;

    // ---- r2 partial: this warp handles broadcast src positions {2w, 2w+1} ----
    // lane-side sentinels: unique negatives per position (pads match nothing)
    const int s0m = (s0 != 0) ? s0 : ~lane;          // in [-32, -1]
    const int s1m = (s1 != 0) ? s1 : ~(lane + 32);   // in [-64, -33]
    int a = 0;
    #pragma unroll
    for (int q = 0; q < 2; q++) {
        int cv0 = __shfl_sync(FULL_MASK, s0m, 2 * warp + q);
        int cv1 = __shfl_sync(FULL_MASK, s1m, 2 * warp + q);
        // broadcast-side pads -> INT_MIN (never equals lane-side sentinel or token)
        cv0 = (cv0 < 0) ? INT_MIN : cv0;
        cv1 = (cv1 < 0) ? INT_MIN : cv1;
        a += (cv0 == s0m) + (cv0 == s1m) + (cv1 == s0m) + (cv1 == s1m);
    }

    const int dot = __reduce_add_sync(FULL_MASK, d);
    const int c2  = __reduce_add_sync(FULL_MASK, c2_val);
    const int r2p = __reduce_add_sync(FULL_MASK, a);

    if (lane == 0) {
        sm_dot[warp] = dot;
        sm_c2[warp]  = c2;
        sm_r2p[warp] = r2p;
    }
    __syncthreads();

    // ---- warp 0: scores + stable descending rank sort (16 lanes) ----
    if (warp == 0 && lane < K_SZ) {
        const int r2 = __reduce_add_sync(0x0000FFFFu, sm_r2p[lane]);
        const float rn = __fsqrt_rn((float)r2);
        const float cn = __fsqrt_rn((float)sm_c2[lane]);
        const float si = __fsub_rn(1.0f,
            __fdiv_rn((float)sm_dot[lane], __fmul_rn(rn, cn)));

        int rank = 0;
        #pragma unroll
        for (int j = 0; j < K_SZ; j++) {
            const float sj = __shfl_sync(0x0000FFFFu, si, j);
            rank += (sj > si) || (sj == si && j < lane);
        }
        sm_rank[lane] = rank;
        if (out_f != nullptr)
            out_f[B_SZ * LC_SZ + B_SZ + b * K_SZ + rank] = si;  // scores_sorted
    }
    __syncthreads();

    // ---- outputs from the winning warp (rank 0) ----
    if (sm_rank[warp] == 0) {
        if (out_f != nullptr) {
            out_f[b * LC_SZ + lane] = (float)t;                 // tokens
            const unsigned nb = __ballot_sync(FULL_MASK, t != 0);
            if (lane == 0)
                out_f[B_SZ * LC_SZ + b] = (float)__popc(nb);    // length
        } else {
            out_i[b * LC_SZ + lane] = t;
        }
    }
}

extern "C" void kernel_launch(void* const* d_in, const int* in_sizes, int n_in,
                              void* d_out, int out_size)
{
    // Identify tensors by element count (robust to scalar inputs in the list):
    //   candidates: 64*16*32 = 32768,  src_ids: 64*64 = 4096
    const int* cand = nullptr;
    const int* src  = nullptr;
    for (int i = 0; i < n_in; i++) {
        if (in_sizes[i] == B_SZ * K_SZ * LC_SZ) cand = (const int*)d_in[i];
        else if (in_sizes[i] == B_SZ * LS_SZ)   src  = (const int*)d_in[i];
    }

    if (out_size == B_SZ * LC_SZ) {
        ngram_rerank_kernel<<<B_SZ, 512>>>(cand, src, nullptr, (int*)d_out);
    } else {
        ngram_rerank_kernel<<<B_SZ, 512>>>(cand, src, (float*)d_out, nullptr);
    }
}